// round 1
// baseline (speedup 1.0000x reference)
#include <cuda_runtime.h>

#define NN 50000
#define NE 800000
#define NG 512
#define DH 128
#define NV 100
#define LN_EPS 1e-5f

// ---------------- scratch (static device globals; no allocs) ----------------
__device__ float g_embW[NV * DH];     // emb @ W1  (100x128)
__device__ float g_dinv[NN];          // rsqrt(deg+1)
__device__ int   g_deg[NN];
__device__ int   g_rs[NN + 1];        // CSR row offsets by dst
__device__ int   g_cur[NN];           // fill cursors
__device__ int   g_col[NE];           // CSR col = src
__device__ float g_h1[NN * DH];       // layer-1 output
__device__ float g_ag2[NN * DH];      // layer-2 aggregated input
__device__ float g_pool[NG * DH];
__device__ float g_cnt[NG];

// ---------------- helpers ----------------
__device__ __forceinline__ float4 ld4(const float* p) {
    return *reinterpret_cast<const float4*>(p);
}
__device__ __forceinline__ void st4(float* p, float4 v) {
    *reinterpret_cast<float4*>(p) = v;
}

// ---------------- kernels ----------------
__global__ void k_zero() {
    int i = blockIdx.x * blockDim.x + threadIdx.x;
    if (i < NG * DH) g_pool[i] = 0.f;
    if (i < NG)      g_cnt[i] = 0.f;
    if (i < NN)      g_deg[i] = 0;
}

// embW = emb @ W1   (100 blocks x 128 threads)
__global__ void k_embW(const float* __restrict__ emb, const float* __restrict__ W1) {
    int r = blockIdx.x, c = threadIdx.x;
    float acc = 0.f;
#pragma unroll 8
    for (int k = 0; k < DH; k++) acc += emb[r * DH + k] * W1[k * DH + c];
    g_embW[r * DH + c] = acc;
}

__global__ void k_count(const int* __restrict__ ei) {
    int e = blockIdx.x * blockDim.x + threadIdx.x;
    if (e < NE) atomicAdd(&g_deg[ei[NE + e]], 1);
}

// single-block exclusive scan over 50000 degrees; also dinv + cursors
__global__ void k_scan() {
    __shared__ int wsum[32];
    const int C = (NN + 1023) / 1024;  // 49
    int t = threadIdx.x, lane = t & 31, wid = t >> 5;
    int beg = t * C;
    int end = beg + C; if (end > NN) end = NN;
    int local = 0;
    for (int i = beg; i < end; i++) local += g_deg[i];
    // warp inclusive scan
    int v = local;
#pragma unroll
    for (int o = 1; o < 32; o <<= 1) {
        int n = __shfl_up_sync(0xffffffffu, v, o);
        if (lane >= o) v += n;
    }
    if (lane == 31) wsum[wid] = v;
    __syncthreads();
    if (wid == 0) {
        int s = wsum[lane];
#pragma unroll
        for (int o = 1; o < 32; o <<= 1) {
            int n = __shfl_up_sync(0xffffffffu, s, o);
            if (lane >= o) s += n;
        }
        wsum[lane] = s;
    }
    __syncthreads();
    int excl = v - local + (wid > 0 ? wsum[wid - 1] : 0);
    int run = excl;
    for (int i = beg; i < end; i++) {
        int c = g_deg[i];
        g_rs[i] = run;
        g_cur[i] = run;
        g_dinv[i] = rsqrtf((float)c + 1.0f);
        run += c;
    }
    if (t == 0) g_rs[NN] = NE;
}

__global__ void k_fill(const int* __restrict__ ei) {
    int e = blockIdx.x * blockDim.x + threadIdx.x;
    if (e < NE) {
        int s = ei[e];
        int d = ei[NE + e];
        int p = atomicAdd(&g_cur[d], 1);
        g_col[p] = s;
    }
}

// layer 1: warp per node. agg of embW[x[src]] rows + self loop, then bias+LN+ReLU.
__global__ void __launch_bounds__(256) k_agg1(const int* __restrict__ x,
                                              const float* __restrict__ b1,
                                              const float* __restrict__ g1,
                                              const float* __restrict__ be1) {
    int w = (blockIdx.x * blockDim.x + threadIdx.x) >> 5;
    int lane = threadIdx.x & 31;
    if (w >= NN) return;
    const int i = w;
    float di = g_dinv[i];
    int xi = __ldg(x + i);
    float4 a = ld4(g_embW + xi * DH + lane * 4);
    float sl = di * di;
    float4 acc = make_float4(a.x * sl, a.y * sl, a.z * sl, a.w * sl);
    int beg = g_rs[i], end = g_rs[i + 1];
    int j = beg;
    for (; j + 4 <= end; j += 4) {
        int s0 = g_col[j], s1 = g_col[j + 1], s2 = g_col[j + 2], s3 = g_col[j + 3];
        float w0 = g_dinv[s0] * di, w1 = g_dinv[s1] * di,
              w2 = g_dinv[s2] * di, w3 = g_dinv[s3] * di;
        int x0 = __ldg(x + s0), x1 = __ldg(x + s1), x2 = __ldg(x + s2), x3 = __ldg(x + s3);
        float4 a0 = ld4(g_embW + x0 * DH + lane * 4);
        float4 a1 = ld4(g_embW + x1 * DH + lane * 4);
        float4 a2 = ld4(g_embW + x2 * DH + lane * 4);
        float4 a3 = ld4(g_embW + x3 * DH + lane * 4);
        acc.x += a0.x * w0 + a1.x * w1 + a2.x * w2 + a3.x * w3;
        acc.y += a0.y * w0 + a1.y * w1 + a2.y * w2 + a3.y * w3;
        acc.z += a0.z * w0 + a1.z * w1 + a2.z * w2 + a3.z * w3;
        acc.w += a0.w * w0 + a1.w * w1 + a2.w * w2 + a3.w * w3;
    }
    for (; j < end; j++) {
        int s = g_col[j];
        float ww = g_dinv[s] * di;
        int xs = __ldg(x + s);
        float4 aa = ld4(g_embW + xs * DH + lane * 4);
        acc.x += aa.x * ww; acc.y += aa.y * ww; acc.z += aa.z * ww; acc.w += aa.w * ww;
    }
    float4 bb = ld4(b1 + lane * 4);
    acc.x += bb.x; acc.y += bb.y; acc.z += bb.z; acc.w += bb.w;
    float s1v = acc.x + acc.y + acc.z + acc.w;
    float s2v = acc.x * acc.x + acc.y * acc.y + acc.z * acc.z + acc.w * acc.w;
#pragma unroll
    for (int o = 16; o > 0; o >>= 1) {
        s1v += __shfl_xor_sync(0xffffffffu, s1v, o);
        s2v += __shfl_xor_sync(0xffffffffu, s2v, o);
    }
    float mu = s1v * (1.0f / DH);
    float var = s2v * (1.0f / DH) - mu * mu;
    float rs = rsqrtf(var + LN_EPS);
    float4 gg = ld4(g1 + lane * 4);
    float4 be = ld4(be1 + lane * 4);
    float4 vo;
    vo.x = fmaxf((acc.x - mu) * rs * gg.x + be.x, 0.f);
    vo.y = fmaxf((acc.y - mu) * rs * gg.y + be.y, 0.f);
    vo.z = fmaxf((acc.z - mu) * rs * gg.z + be.z, 0.f);
    vo.w = fmaxf((acc.w - mu) * rs * gg.w + be.w, 0.f);
    st4(g_h1 + i * DH + lane * 4, vo);
}

// layer 2 aggregation: warp per node over h1 rows (L2-resident gathers)
__global__ void __launch_bounds__(256) k_agg2() {
    int w = (blockIdx.x * blockDim.x + threadIdx.x) >> 5;
    int lane = threadIdx.x & 31;
    if (w >= NN) return;
    const int i = w;
    float di = g_dinv[i];
    float4 a = ld4(g_h1 + i * DH + lane * 4);
    float sl = di * di;
    float4 acc = make_float4(a.x * sl, a.y * sl, a.z * sl, a.w * sl);
    int beg = g_rs[i], end = g_rs[i + 1];
    int j = beg;
    for (; j + 4 <= end; j += 4) {
        int s0 = g_col[j], s1 = g_col[j + 1], s2 = g_col[j + 2], s3 = g_col[j + 3];
        float w0 = g_dinv[s0] * di, w1 = g_dinv[s1] * di,
              w2 = g_dinv[s2] * di, w3 = g_dinv[s3] * di;
        float4 a0 = ld4(g_h1 + s0 * DH + lane * 4);
        float4 a1 = ld4(g_h1 + s1 * DH + lane * 4);
        float4 a2 = ld4(g_h1 + s2 * DH + lane * 4);
        float4 a3 = ld4(g_h1 + s3 * DH + lane * 4);
        acc.x += a0.x * w0 + a1.x * w1 + a2.x * w2 + a3.x * w3;
        acc.y += a0.y * w0 + a1.y * w1 + a2.y * w2 + a3.y * w3;
        acc.z += a0.z * w0 + a1.z * w1 + a2.z * w2 + a3.z * w3;
        acc.w += a0.w * w0 + a1.w * w1 + a2.w * w2 + a3.w * w3;
    }
    for (; j < end; j++) {
        int s = g_col[j];
        float ww = g_dinv[s] * di;
        float4 aa = ld4(g_h1 + s * DH + lane * 4);
        acc.x += aa.x * ww; acc.y += aa.y * ww; acc.z += aa.z * ww; acc.w += aa.w * ww;
    }
    st4(g_ag2 + i * DH + lane * 4, acc);
}

// layer-2 GEMM (ag2 @ W2) with fused bias + LN + ReLU + mean-pool atomics.
// block = 256 threads = 8 warps, 32 nodes per block, 4 nodes per warp.
__global__ void __launch_bounds__(256) k_gemm2(const float* __restrict__ W2,
                                               const float* __restrict__ b2,
                                               const float* __restrict__ g2,
                                               const float* __restrict__ be2,
                                               const int* __restrict__ batch) {
    __shared__ float sh[32 * DH];
    int tid = threadIdx.x;
    int nb = blockIdx.x * 32;
    // stage 32 node rows of ag2
#pragma unroll
    for (int q = 0; q < 4; q++) {
        int idx = tid + q * 256;          // float4 index
        int row = idx >> 5;               // 32 float4 per row
        int ci = idx & 31;
        int n = nb + row;
        float4 v = (n < NN) ? ld4(g_ag2 + n * DH + ci * 4) : make_float4(0, 0, 0, 0);
        st4(sh + idx * 4, v);
    }
    __syncthreads();
    int w = tid >> 5, lane = tid & 31;
    float4 acc0 = make_float4(0, 0, 0, 0), acc1 = acc0, acc2 = acc0, acc3 = acc0;
    const float* shb = sh + (w * 4) * DH;
#pragma unroll 4
    for (int k = 0; k < DH; k++) {
        float4 wr = ld4(W2 + k * DH + lane * 4);
        float h0 = shb[k], h1 = shb[DH + k], h2 = shb[2 * DH + k], h3 = shb[3 * DH + k];
        acc0.x += wr.x * h0; acc0.y += wr.y * h0; acc0.z += wr.z * h0; acc0.w += wr.w * h0;
        acc1.x += wr.x * h1; acc1.y += wr.y * h1; acc1.z += wr.z * h1; acc1.w += wr.w * h1;
        acc2.x += wr.x * h2; acc2.y += wr.y * h2; acc2.z += wr.z * h2; acc2.w += wr.w * h2;
        acc3.x += wr.x * h3; acc3.y += wr.y * h3; acc3.z += wr.z * h3; acc3.w += wr.w * h3;
    }
    float4 bb = ld4(b2 + lane * 4);
    float4 gg = ld4(g2 + lane * 4);
    float4 be = ld4(be2 + lane * 4);
    float4 vv[4];
    int gid[4];
    float4 accs[4] = {acc0, acc1, acc2, acc3};
#pragma unroll
    for (int q = 0; q < 4; q++) {
        int n = nb + w * 4 + q;
        float4 v = accs[q];
        v.x += bb.x; v.y += bb.y; v.z += bb.z; v.w += bb.w;
        float s1v = v.x + v.y + v.z + v.w;
        float s2v = v.x * v.x + v.y * v.y + v.z * v.z + v.w * v.w;
#pragma unroll
        for (int o = 16; o > 0; o >>= 1) {
            s1v += __shfl_xor_sync(0xffffffffu, s1v, o);
            s2v += __shfl_xor_sync(0xffffffffu, s2v, o);
        }
        float mu = s1v * (1.0f / DH);
        float var = s2v * (1.0f / DH) - mu * mu;
        float rs = rsqrtf(var + LN_EPS);
        vv[q].x = fmaxf((v.x - mu) * rs * gg.x + be.x, 0.f);
        vv[q].y = fmaxf((v.y - mu) * rs * gg.y + be.y, 0.f);
        vv[q].z = fmaxf((v.z - mu) * rs * gg.z + be.z, 0.f);
        vv[q].w = fmaxf((v.w - mu) * rs * gg.w + be.w, 0.f);
        gid[q] = (n < NN) ? __ldg(batch + n) : -1;
    }
    // merge consecutive same-graph nodes before atomics (batch is sorted)
    float4 run = vv[0];
    int rg = gid[0];
    float rc = 1.f;
#pragma unroll
    for (int q = 1; q < 4; q++) {
        if (gid[q] == rg) {
            run.x += vv[q].x; run.y += vv[q].y; run.z += vv[q].z; run.w += vv[q].w;
            rc += 1.f;
        } else {
            if (rg >= 0) {
                float* p = g_pool + rg * DH + lane * 4;
                atomicAdd(p + 0, run.x); atomicAdd(p + 1, run.y);
                atomicAdd(p + 2, run.z); atomicAdd(p + 3, run.w);
                if (lane == 0) atomicAdd(&g_cnt[rg], rc);
            }
            run = vv[q]; rg = gid[q]; rc = 1.f;
        }
    }
    if (rg >= 0) {
        float* p = g_pool + rg * DH + lane * 4;
        atomicAdd(p + 0, run.x); atomicAdd(p + 1, run.y);
        atomicAdd(p + 2, run.z); atomicAdd(p + 3, run.w);
        if (lane == 0) atomicAdd(&g_cnt[rg], rc);
    }
}

// final: out[g] = mean-pooled dot fcW + fcb
__global__ void k_out(const float* __restrict__ fcW, const float* __restrict__ fcb,
                      float* __restrict__ out) {
    int w = (blockIdx.x * blockDim.x + threadIdx.x) >> 5;
    int lane = threadIdx.x & 31;
    if (w >= NG) return;
    float4 p = ld4(g_pool + w * DH + lane * 4);
    float4 f = ld4(fcW + lane * 4);
    float part = p.x * f.x + p.y * f.y + p.z * f.z + p.w * f.w;
#pragma unroll
    for (int o = 16; o > 0; o >>= 1) part += __shfl_xor_sync(0xffffffffu, part, o);
    if (lane == 0) {
        float c = g_cnt[w];
        out[w] = part / fmaxf(c, 1.0f) + fcb[0];
    }
}

// ---------------- launch ----------------
extern "C" void kernel_launch(void* const* d_in, const int* in_sizes, int n_in,
                              void* d_out, int out_size) {
    const int*   x     = (const int*)d_in[0];
    const int*   ei    = (const int*)d_in[1];
    const int*   batch = (const int*)d_in[2];
    const float* emb   = (const float*)d_in[3];
    const float* W1    = (const float*)d_in[4];
    const float* b1    = (const float*)d_in[5];
    const float* g1    = (const float*)d_in[6];
    const float* be1   = (const float*)d_in[7];
    const float* W2    = (const float*)d_in[8];
    const float* b2    = (const float*)d_in[9];
    const float* g2    = (const float*)d_in[10];
    const float* be2   = (const float*)d_in[11];
    const float* fcW   = (const float*)d_in[12];
    const float* fcb   = (const float*)d_in[13];
    float* out = (float*)d_out;

    k_zero<<<(NG * DH + 255) / 256, 256>>>();
    k_embW<<<NV, DH>>>(emb, W1);
    k_count<<<(NE + 255) / 256, 256>>>(ei);
    k_scan<<<1, 1024>>>();
    k_fill<<<(NE + 255) / 256, 256>>>(ei);
    k_agg1<<<(NN * 32 + 255) / 256, 256>>>(x, b1, g1, be1);
    k_agg2<<<(NN * 32 + 255) / 256, 256>>>();
    k_gemm2<<<(NN + 31) / 32, 256>>>(W2, b2, g2, be2, batch);
    k_out<<<(NG * 32 + 255) / 256, 256>>>(fcW, fcb, out);
}

// round 2
// speedup vs baseline: 1.6584x; 1.6584x over previous
#include <cuda_runtime.h>

#define NN 50000
#define NE 800000
#define NG 512
#define DH 128
#define NV 100
#define LN_EPS 1e-5f

#define SCAN_B 256
#define NBLK ((NN + SCAN_B - 1) / SCAN_B)   // 196

// ---------------- scratch (static device globals; no allocs) ----------------
__device__ float g_embW[NV * DH];     // emb @ W1  (100x128)
__device__ float g_dinv[NN];          // rsqrt(deg+1)
__device__ int   g_deg[NN];
__device__ int   g_rs[NN + 1];        // CSR row offsets by dst
__device__ int   g_cur[NN];           // fill cursors
__device__ int   g_col[NE];           // CSR col = src
__device__ int   g_bsum[NBLK];
__device__ int   g_boff[NBLK];
__device__ float g_h1[NN * DH];       // layer-1 output
__device__ float g_ag2[NN * DH];      // layer-2 aggregated input
__device__ float g_pool[NG * DH];
__device__ float g_cnt[NG];

// ---------------- helpers ----------------
__device__ __forceinline__ float4 ld4(const float* p) {
    return *reinterpret_cast<const float4*>(p);
}
__device__ __forceinline__ void st4(float* p, float4 v) {
    *reinterpret_cast<float4*>(p) = v;
}

// ---------------- kernels ----------------
__global__ void k_zero() {
    int i = blockIdx.x * blockDim.x + threadIdx.x;
    if (i < NG * DH) g_pool[i] = 0.f;
    if (i < NG)      g_cnt[i] = 0.f;
    if (i < NN)      g_deg[i] = 0;
}

// embW = emb @ W1   (100 blocks x 128 threads)
__global__ void k_embW(const float* __restrict__ emb, const float* __restrict__ W1) {
    int r = blockIdx.x, c = threadIdx.x;
    float acc = 0.f;
#pragma unroll 8
    for (int k = 0; k < DH; k++) acc += emb[r * DH + k] * W1[k * DH + c];
    g_embW[r * DH + c] = acc;
}

__global__ void k_count(const int* __restrict__ ei) {
    int e = blockIdx.x * blockDim.x + threadIdx.x;
    if (e < NE) atomicAdd(&g_deg[ei[NE + e]], 1);
}

// phase 1: per-block degree sums
__global__ void __launch_bounds__(SCAN_B) k_partial() {
    int i = blockIdx.x * SCAN_B + threadIdx.x;
    int lane = threadIdx.x & 31, wid = threadIdx.x >> 5;
    int v = (i < NN) ? g_deg[i] : 0;
#pragma unroll
    for (int o = 16; o > 0; o >>= 1) v += __shfl_xor_sync(0xffffffffu, v, o);
    __shared__ int ws[8];
    if (lane == 0) ws[wid] = v;
    __syncthreads();
    if (threadIdx.x == 0) {
        int s = 0;
#pragma unroll
        for (int k = 0; k < 8; k++) s += ws[k];
        g_bsum[blockIdx.x] = s;
    }
}

// phase 2: one block exclusive-scans the 196 block sums
__global__ void __launch_bounds__(SCAN_B) k_scanb() {
    int t = threadIdx.x, lane = t & 31, wid = t >> 5;
    int v = (t < NBLK) ? g_bsum[t] : 0;
    int inc = v;
#pragma unroll
    for (int o = 1; o < 32; o <<= 1) {
        int n = __shfl_up_sync(0xffffffffu, inc, o);
        if (lane >= o) inc += n;
    }
    __shared__ int ws[8];
    if (lane == 31) ws[wid] = inc;
    __syncthreads();
    if (wid == 0 && lane < 8) {
        int s = ws[lane];
#pragma unroll
        for (int o = 1; o < 8; o <<= 1) {
            int n = __shfl_up_sync(0xffu, s, o);
            if (lane >= o) s += n;
        }
        ws[lane] = s;
    }
    __syncthreads();
    int excl = inc - v + (wid > 0 ? ws[wid - 1] : 0);
    if (t < NBLK) g_boff[t] = excl;
}

// phase 3: in-block exclusive scan + block offset; write rs/cur/dinv
__global__ void __launch_bounds__(SCAN_B) k_write() {
    int i = blockIdx.x * SCAN_B + threadIdx.x;
    int lane = threadIdx.x & 31, wid = threadIdx.x >> 5;
    int v = (i < NN) ? g_deg[i] : 0;
    int inc = v;
#pragma unroll
    for (int o = 1; o < 32; o <<= 1) {
        int n = __shfl_up_sync(0xffffffffu, inc, o);
        if (lane >= o) inc += n;
    }
    __shared__ int ws[8];
    if (lane == 31) ws[wid] = inc;
    __syncthreads();
    if (wid == 0 && lane < 8) {
        int s = ws[lane];
#pragma unroll
        for (int o = 1; o < 8; o <<= 1) {
            int n = __shfl_up_sync(0xffu, s, o);
            if (lane >= o) s += n;
        }
        ws[lane] = s;
    }
    __syncthreads();
    int excl = inc - v + (wid > 0 ? ws[wid - 1] : 0) + g_boff[blockIdx.x];
    if (i < NN) {
        g_rs[i] = excl;
        g_cur[i] = excl;
        g_dinv[i] = rsqrtf((float)v + 1.0f);
    }
    if (i == 0) g_rs[NN] = NE;
}

__global__ void k_fill(const int* __restrict__ ei) {
    int e = blockIdx.x * blockDim.x + threadIdx.x;
    if (e < NE) {
        int s = ei[e];
        int d = ei[NE + e];
        int p = atomicAdd(&g_cur[d], 1);
        g_col[p] = s;
    }
}

// layer 1: warp per node. agg of embW[x[src]] rows + self loop, then bias+LN+ReLU.
__global__ void __launch_bounds__(256) k_agg1(const int* __restrict__ x,
                                              const float* __restrict__ b1,
                                              const float* __restrict__ g1,
                                              const float* __restrict__ be1) {
    int w = (blockIdx.x * blockDim.x + threadIdx.x) >> 5;
    int lane = threadIdx.x & 31;
    if (w >= NN) return;
    const int i = w;
    float di = g_dinv[i];
    int xi = __ldg(x + i);
    float4 a = ld4(g_embW + xi * DH + lane * 4);
    float sl = di * di;
    float4 acc = make_float4(a.x * sl, a.y * sl, a.z * sl, a.w * sl);
    int beg = g_rs[i], end = g_rs[i + 1];
    int j = beg;
    for (; j + 4 <= end; j += 4) {
        int s0 = g_col[j], s1 = g_col[j + 1], s2 = g_col[j + 2], s3 = g_col[j + 3];
        float w0 = g_dinv[s0] * di, w1 = g_dinv[s1] * di,
              w2 = g_dinv[s2] * di, w3 = g_dinv[s3] * di;
        int x0 = __ldg(x + s0), x1 = __ldg(x + s1), x2 = __ldg(x + s2), x3 = __ldg(x + s3);
        float4 a0 = ld4(g_embW + x0 * DH + lane * 4);
        float4 a1 = ld4(g_embW + x1 * DH + lane * 4);
        float4 a2 = ld4(g_embW + x2 * DH + lane * 4);
        float4 a3 = ld4(g_embW + x3 * DH + lane * 4);
        acc.x += a0.x * w0 + a1.x * w1 + a2.x * w2 + a3.x * w3;
        acc.y += a0.y * w0 + a1.y * w1 + a2.y * w2 + a3.y * w3;
        acc.z += a0.z * w0 + a1.z * w1 + a2.z * w2 + a3.z * w3;
        acc.w += a0.w * w0 + a1.w * w1 + a2.w * w2 + a3.w * w3;
    }
    for (; j < end; j++) {
        int s = g_col[j];
        float ww = g_dinv[s] * di;
        int xs = __ldg(x + s);
        float4 aa = ld4(g_embW + xs * DH + lane * 4);
        acc.x += aa.x * ww; acc.y += aa.y * ww; acc.z += aa.z * ww; acc.w += aa.w * ww;
    }
    float4 bb = ld4(b1 + lane * 4);
    acc.x += bb.x; acc.y += bb.y; acc.z += bb.z; acc.w += bb.w;
    float s1v = acc.x + acc.y + acc.z + acc.w;
    float s2v = acc.x * acc.x + acc.y * acc.y + acc.z * acc.z + acc.w * acc.w;
#pragma unroll
    for (int o = 16; o > 0; o >>= 1) {
        s1v += __shfl_xor_sync(0xffffffffu, s1v, o);
        s2v += __shfl_xor_sync(0xffffffffu, s2v, o);
    }
    float mu = s1v * (1.0f / DH);
    float var = s2v * (1.0f / DH) - mu * mu;
    float rs = rsqrtf(var + LN_EPS);
    float4 gg = ld4(g1 + lane * 4);
    float4 be = ld4(be1 + lane * 4);
    float4 vo;
    vo.x = fmaxf((acc.x - mu) * rs * gg.x + be.x, 0.f);
    vo.y = fmaxf((acc.y - mu) * rs * gg.y + be.y, 0.f);
    vo.z = fmaxf((acc.z - mu) * rs * gg.z + be.z, 0.f);
    vo.w = fmaxf((acc.w - mu) * rs * gg.w + be.w, 0.f);
    st4(g_h1 + i * DH + lane * 4, vo);
}

// layer 2 aggregation: warp per node over h1 rows (L2-resident gathers)
__global__ void __launch_bounds__(256) k_agg2() {
    int w = (blockIdx.x * blockDim.x + threadIdx.x) >> 5;
    int lane = threadIdx.x & 31;
    if (w >= NN) return;
    const int i = w;
    float di = g_dinv[i];
    float4 a = ld4(g_h1 + i * DH + lane * 4);
    float sl = di * di;
    float4 acc = make_float4(a.x * sl, a.y * sl, a.z * sl, a.w * sl);
    int beg = g_rs[i], end = g_rs[i + 1];
    int j = beg;
    for (; j + 4 <= end; j += 4) {
        int s0 = g_col[j], s1 = g_col[j + 1], s2 = g_col[j + 2], s3 = g_col[j + 3];
        float w0 = g_dinv[s0] * di, w1 = g_dinv[s1] * di,
              w2 = g_dinv[s2] * di, w3 = g_dinv[s3] * di;
        float4 a0 = ld4(g_h1 + s0 * DH + lane * 4);
        float4 a1 = ld4(g_h1 + s1 * DH + lane * 4);
        float4 a2 = ld4(g_h1 + s2 * DH + lane * 4);
        float4 a3 = ld4(g_h1 + s3 * DH + lane * 4);
        acc.x += a0.x * w0 + a1.x * w1 + a2.x * w2 + a3.x * w3;
        acc.y += a0.y * w0 + a1.y * w1 + a2.y * w2 + a3.y * w3;
        acc.z += a0.z * w0 + a1.z * w1 + a2.z * w2 + a3.z * w3;
        acc.w += a0.w * w0 + a1.w * w1 + a2.w * w2 + a3.w * w3;
    }
    for (; j < end; j++) {
        int s = g_col[j];
        float ww = g_dinv[s] * di;
        float4 aa = ld4(g_h1 + s * DH + lane * 4);
        acc.x += aa.x * ww; acc.y += aa.y * ww; acc.z += aa.z * ww; acc.w += aa.w * ww;
    }
    st4(g_ag2 + i * DH + lane * 4, acc);
}

// layer-2 GEMM (ag2 @ W2) with fused bias + LN + ReLU + mean-pool atomics.
__global__ void __launch_bounds__(256) k_gemm2(const float* __restrict__ W2,
                                               const float* __restrict__ b2,
                                               const float* __restrict__ g2,
                                               const float* __restrict__ be2,
                                               const int* __restrict__ batch) {
    __shared__ float sh[32 * DH];
    int tid = threadIdx.x;
    int nb = blockIdx.x * 32;
#pragma unroll
    for (int q = 0; q < 4; q++) {
        int idx = tid + q * 256;
        int row = idx >> 5;
        int ci = idx & 31;
        int n = nb + row;
        float4 v = (n < NN) ? ld4(g_ag2 + n * DH + ci * 4) : make_float4(0, 0, 0, 0);
        st4(sh + idx * 4, v);
    }
    __syncthreads();
    int w = tid >> 5, lane = tid & 31;
    float4 acc0 = make_float4(0, 0, 0, 0), acc1 = acc0, acc2 = acc0, acc3 = acc0;
    const float* shb = sh + (w * 4) * DH;
#pragma unroll 4
    for (int k = 0; k < DH; k++) {
        float4 wr = ld4(W2 + k * DH + lane * 4);
        float h0 = shb[k], h1 = shb[DH + k], h2 = shb[2 * DH + k], h3 = shb[3 * DH + k];
        acc0.x += wr.x * h0; acc0.y += wr.y * h0; acc0.z += wr.z * h0; acc0.w += wr.w * h0;
        acc1.x += wr.x * h1; acc1.y += wr.y * h1; acc1.z += wr.z * h1; acc1.w += wr.w * h1;
        acc2.x += wr.x * h2; acc2.y += wr.y * h2; acc2.z += wr.z * h2; acc2.w += wr.w * h2;
        acc3.x += wr.x * h3; acc3.y += wr.y * h3; acc3.z += wr.z * h3; acc3.w += wr.w * h3;
    }
    float4 bb = ld4(b2 + lane * 4);
    float4 gg = ld4(g2 + lane * 4);
    float4 be = ld4(be2 + lane * 4);
    float4 vv[4];
    int gid[4];
    float4 accs[4] = {acc0, acc1, acc2, acc3};
#pragma unroll
    for (int q = 0; q < 4; q++) {
        int n = nb + w * 4 + q;
        float4 v = accs[q];
        v.x += bb.x; v.y += bb.y; v.z += bb.z; v.w += bb.w;
        float s1v = v.x + v.y + v.z + v.w;
        float s2v = v.x * v.x + v.y * v.y + v.z * v.z + v.w * v.w;
#pragma unroll
        for (int o = 16; o > 0; o >>= 1) {
            s1v += __shfl_xor_sync(0xffffffffu, s1v, o);
            s2v += __shfl_xor_sync(0xffffffffu, s2v, o);
        }
        float mu = s1v * (1.0f / DH);
        float var = s2v * (1.0f / DH) - mu * mu;
        float rs = rsqrtf(var + LN_EPS);
        vv[q].x = fmaxf((v.x - mu) * rs * gg.x + be.x, 0.f);
        vv[q].y = fmaxf((v.y - mu) * rs * gg.y + be.y, 0.f);
        vv[q].z = fmaxf((v.z - mu) * rs * gg.z + be.z, 0.f);
        vv[q].w = fmaxf((v.w - mu) * rs * gg.w + be.w, 0.f);
        gid[q] = (n < NN) ? __ldg(batch + n) : -1;
    }
    float4 run = vv[0];
    int rg = gid[0];
    float rc = 1.f;
#pragma unroll
    for (int q = 1; q < 4; q++) {
        if (gid[q] == rg) {
            run.x += vv[q].x; run.y += vv[q].y; run.z += vv[q].z; run.w += vv[q].w;
            rc += 1.f;
        } else {
            if (rg >= 0) {
                float* p = g_pool + rg * DH + lane * 4;
                atomicAdd(p + 0, run.x); atomicAdd(p + 1, run.y);
                atomicAdd(p + 2, run.z); atomicAdd(p + 3, run.w);
                if (lane == 0) atomicAdd(&g_cnt[rg], rc);
            }
            run = vv[q]; rg = gid[q]; rc = 1.f;
        }
    }
    if (rg >= 0) {
        float* p = g_pool + rg * DH + lane * 4;
        atomicAdd(p + 0, run.x); atomicAdd(p + 1, run.y);
        atomicAdd(p + 2, run.z); atomicAdd(p + 3, run.w);
        if (lane == 0) atomicAdd(&g_cnt[rg], rc);
    }
}

// final: out[g] = mean-pooled dot fcW + fcb
__global__ void k_out(const float* __restrict__ fcW, const float* __restrict__ fcb,
                      float* __restrict__ out) {
    int w = (blockIdx.x * blockDim.x + threadIdx.x) >> 5;
    int lane = threadIdx.x & 31;
    if (w >= NG) return;
    float4 p = ld4(g_pool + w * DH + lane * 4);
    float4 f = ld4(fcW + lane * 4);
    float part = p.x * f.x + p.y * f.y + p.z * f.z + p.w * f.w;
#pragma unroll
    for (int o = 16; o > 0; o >>= 1) part += __shfl_xor_sync(0xffffffffu, part, o);
    if (lane == 0) {
        float c = g_cnt[w];
        out[w] = part / fmaxf(c, 1.0f) + fcb[0];
    }
}

// ---------------- launch ----------------
extern "C" void kernel_launch(void* const* d_in, const int* in_sizes, int n_in,
                              void* d_out, int out_size) {
    const int*   x     = (const int*)d_in[0];
    const int*   ei    = (const int*)d_in[1];
    const int*   batch = (const int*)d_in[2];
    const float* emb   = (const float*)d_in[3];
    const float* W1    = (const float*)d_in[4];
    const float* b1    = (const float*)d_in[5];
    const float* g1    = (const float*)d_in[6];
    const float* be1   = (const float*)d_in[7];
    const float* W2    = (const float*)d_in[8];
    const float* b2    = (const float*)d_in[9];
    const float* g2    = (const float*)d_in[10];
    const float* be2   = (const float*)d_in[11];
    const float* fcW   = (const float*)d_in[12];
    const float* fcb   = (const float*)d_in[13];
    float* out = (float*)d_out;

    k_zero<<<(NG * DH + 255) / 256, 256>>>();
    k_embW<<<NV, DH>>>(emb, W1);
    k_count<<<(NE + 255) / 256, 256>>>(ei);
    k_partial<<<NBLK, SCAN_B>>>();
    k_scanb<<<1, SCAN_B>>>();
    k_write<<<NBLK, SCAN_B>>>();
    k_fill<<<(NE + 255) / 256, 256>>>(ei);
    k_agg1<<<(NN * 32 + 255) / 256, 256>>>(x, b1, g1, be1);
    k_agg2<<<(NN * 32 + 255) / 256, 256>>>();
    k_gemm2<<<(NN + 31) / 32, 256>>>(W2, b2, g2, be2, batch);
    k_out<<<(NG * 32 + 255) / 256, 256>>>(fcW, fcb, out);
}